// round 1
// baseline (speedup 1.0000x reference)
#include <cuda_runtime.h>

// DiffJPEG: per-8x8-block DCT -> quantize(round)/dequantize -> IDCT.
// Input/Output: (32, 3, 512, 512) fp32. One thread owns one 8x8 block,
// fully register-resident, separable 8-point DCT with even/odd symmetry.

#define C1 0.4903926402f   // 0.5*cos(1*pi/16)
#define C2 0.4619397663f   // 0.5*cos(2*pi/16)
#define C3 0.4157348062f   // 0.5*cos(3*pi/16)
#define C4 0.3535533906f   // 0.5*cos(4*pi/16) == sqrt(1/8)
#define C5 0.2777851165f   // 0.5*cos(5*pi/16)
#define C6 0.1913417162f   // 0.5*cos(6*pi/16)
#define C7 0.0975451610f   // 0.5*cos(7*pi/16)

// Forward 8-point DCT-II (orthonormal), in place.
__device__ __forceinline__ void dct8(float& x0, float& x1, float& x2, float& x3,
                                     float& x4, float& x5, float& x6, float& x7) {
    float s0 = x0 + x7, s1 = x1 + x6, s2 = x2 + x5, s3 = x3 + x4;
    float d0 = x0 - x7, d1 = x1 - x6, d2 = x2 - x5, d3 = x3 - x4;
    float e0 = s0 + s3, e1 = s1 + s2;
    float f0 = s0 - s3, f1 = s1 - s2;
    x0 = C4 * (e0 + e1);
    x4 = C4 * (e0 - e1);
    x2 = C2 * f0 + C6 * f1;
    x6 = C6 * f0 - C2 * f1;
    x1 = C1 * d0 + C3 * d1 + C5 * d2 + C7 * d3;
    x3 = C3 * d0 - C7 * d1 - C1 * d2 - C5 * d3;
    x5 = C5 * d0 - C1 * d1 + C7 * d2 + C3 * d3;
    x7 = C7 * d0 - C5 * d1 + C3 * d2 - C1 * d3;
}

// Inverse 8-point DCT (transpose of the above), in place.
__device__ __forceinline__ void idct8(float& x0, float& x1, float& x2, float& x3,
                                      float& x4, float& x5, float& x6, float& x7) {
    float a = C4 * (x0 + x4);
    float b = C4 * (x0 - x4);
    float e0 = a + C2 * x2 + C6 * x6;
    float e3 = a - C2 * x2 - C6 * x6;
    float e1 = b + C6 * x2 - C2 * x6;
    float e2 = b - C6 * x2 + C2 * x6;
    float o0 = C1 * x1 + C3 * x3 + C5 * x5 + C7 * x7;
    float o1 = C3 * x1 - C7 * x3 - C1 * x5 - C5 * x7;
    float o2 = C5 * x1 - C1 * x3 + C7 * x5 + C3 * x7;
    float o3 = C7 * x1 - C5 * x3 + C3 * x5 - C1 * x7;
    x0 = e0 + o0;  x7 = e0 - o0;
    x1 = e1 + o1;  x6 = e1 - o1;
    x2 = e2 + o2;  x5 = e2 - o2;
    x3 = e3 + o3;  x4 = e3 - o3;
}

static __device__ __constant__ const float kQ[64] = {
    16.f, 11.f, 10.f, 16.f, 24.f,  40.f,  51.f,  61.f,
    12.f, 12.f, 14.f, 19.f, 26.f,  58.f,  60.f,  55.f,
    14.f, 13.f, 16.f, 24.f, 40.f,  57.f,  69.f,  56.f,
    14.f, 17.f, 22.f, 29.f, 51.f,  87.f,  80.f,  62.f,
    18.f, 22.f, 37.f, 56.f, 68.f, 109.f, 103.f,  77.f,
    24.f, 35.f, 55.f, 64.f, 81.f, 104.f, 113.f,  92.f,
    49.f, 64.f, 78.f, 87.f, 103.f,121.f, 120.f, 101.f,
    72.f, 92.f, 95.f, 98.f, 112.f,100.f, 103.f,  99.f
};

static constexpr int kW = 512;              // image width
static constexpr int kBlocksPerImg = 64 * 64;
static constexpr int kNumBlocks = 32 * 3 * kBlocksPerImg;   // 393216

__global__ __launch_bounds__(256)
void diffjpeg_kernel(const float* __restrict__ in, float* __restrict__ out) {
    int t = blockIdx.x * blockDim.x + threadIdx.x;
    if (t >= kNumBlocks) return;

    int bc  = t & 63;          // block column (0..63)
    int br  = (t >> 6) & 63;   // block row    (0..63)
    int img = t >> 12;         // (b*3 + c)    (0..95)

    size_t base = ((size_t)img << 18) + ((size_t)(br << 3)) * kW + (bc << 3);
    const float* p = in + base;
    float* q = out + base;

    float x[8][8];

    // Load 8x8 block: 16 independent 128-bit loads (front-batched -> high MLP).
#pragma unroll
    for (int r = 0; r < 8; r++) {
        float4 a = *reinterpret_cast<const float4*>(p + (size_t)r * kW);
        float4 b = *reinterpret_cast<const float4*>(p + (size_t)r * kW + 4);
        x[r][0] = a.x; x[r][1] = a.y; x[r][2] = a.z; x[r][3] = a.w;
        x[r][4] = b.x; x[r][5] = b.y; x[r][6] = b.z; x[r][7] = b.w;
    }

    // Forward 2D DCT: columns then rows (separable).
#pragma unroll
    for (int c = 0; c < 8; c++)
        dct8(x[0][c], x[1][c], x[2][c], x[3][c], x[4][c], x[5][c], x[6][c], x[7][c]);
#pragma unroll
    for (int r = 0; r < 8; r++)
        dct8(x[r][0], x[r][1], x[r][2], x[r][3], x[r][4], x[r][5], x[r][6], x[r][7]);

    // Quantize (round-half-to-even, matching jnp.round) and dequantize.
#pragma unroll
    for (int r = 0; r < 8; r++) {
#pragma unroll
        for (int c = 0; c < 8; c++) {
            float qv = kQ[r * 8 + c];
            x[r][c] = rintf(x[r][c] / qv) * qv;
        }
    }

    // Inverse 2D DCT: columns then rows.
#pragma unroll
    for (int c = 0; c < 8; c++)
        idct8(x[0][c], x[1][c], x[2][c], x[3][c], x[4][c], x[5][c], x[6][c], x[7][c]);
#pragma unroll
    for (int r = 0; r < 8; r++)
        idct8(x[r][0], x[r][1], x[r][2], x[r][3], x[r][4], x[r][5], x[r][6], x[r][7]);

    // Store 8x8 block.
#pragma unroll
    for (int r = 0; r < 8; r++) {
        float4 a = make_float4(x[r][0], x[r][1], x[r][2], x[r][3]);
        float4 b = make_float4(x[r][4], x[r][5], x[r][6], x[r][7]);
        *reinterpret_cast<float4*>(q + (size_t)r * kW)     = a;
        *reinterpret_cast<float4*>(q + (size_t)r * kW + 4) = b;
    }
}

extern "C" void kernel_launch(void* const* d_in, const int* in_sizes, int n_in,
                              void* d_out, int out_size) {
    const float* img = (const float*)d_in[0];
    float* out = (float*)d_out;
    int threads = 256;
    int blocks = (kNumBlocks + threads - 1) / threads;   // 1536
    diffjpeg_kernel<<<blocks, threads>>>(img, out);
}